// round 6
// baseline (speedup 1.0000x reference)
#include <cuda_runtime.h>
#include <cstdint>
#include <math.h>

#define NN   256
#define HWN  196
#define CC   512
#define HWH  98            // real hw rows per half
#define HWP  112           // padded hw rows per half
#define EPS_POS_F 0.65f
#define EPS_NEG_F 0.40f
#define INV_TAU   (1.0f/0.03f)
#define TEMP_F    0.07f

// ---- smem layout (bytes), main kernel ----
#define A_ST   20480        // 256 rows x 80 B (64 int8 data + pad)
#define B_ST   8960         // 112 rows x 80 B
#define STAGE  (A_ST + B_ST)            // 29440
#define SM_A(st)  ((st)*STAGE)
#define SM_B(st)  ((st)*STAGE + A_ST)
#define SM_SA   88320       // float[256] audio scales
#define SM_SF   89344       // float[112] frame scales
#define SM_SNUM 89792       // float[256]
#define SM_SDEN 90816       // float[256]
#define SM_SNEG 91840       // float[2]
#define SMEM_TOTAL 91856

// ---- scratch globals ----
__device__ int8_t g_qf[(size_t)NN * HWN * CC];   // quantized frame rows
__device__ float  g_sf[NN * HWN];                // frame row scales (incl rnorm)
__device__ int8_t g_qa[NN * CC];                 // quantized audio rows
__device__ float  g_sa[NN];                      // audio row scales (incl rnorm)
__device__ float g_pn[2 * NN * NN];
__device__ float g_pd[2 * NN * NN];
__device__ float g_qn[2 * NN];
__device__ float g_qd[2 * NN];
__device__ float g_Pid[NN];
__device__ float g_Nid[NN];

__device__ __forceinline__ uint32_t smem_u32(const void* p) {
    uint32_t a;
    asm("{ .reg .u64 t; cvta.to.shared.u64 t, %1; cvt.u32.u64 %0, t; }" : "=r"(a) : "l"(p));
    return a;
}

#define CP_ASYNC16(dst, src) \
    asm volatile("cp.async.cg.shared.global [%0], [%1], 16;" :: "r"(dst), "l"(src) : "memory")
#define CP_ASYNC16Z(dst, src, sz) \
    asm volatile("cp.async.cg.shared.global [%0], [%1], 16, %2;" :: "r"(dst), "l"(src), "r"(sz) : "memory")
#define CP_COMMIT() asm volatile("cp.async.commit_group;" ::: "memory")
#define CP_WAIT2()  asm volatile("cp.async.wait_group 2;" ::: "memory")

#define MMA_S8(d, a, b0, b1)                                                    \
    asm volatile("mma.sync.aligned.m16n8k32.row.col.s32.s8.s8.s32 "             \
        "{%0,%1,%2,%3}, {%4,%5,%6,%7}, {%8,%9}, {%0,%1,%2,%3};"                 \
        : "+r"((d)[0]), "+r"((d)[1]), "+r"((d)[2]), "+r"((d)[3])                \
        : "r"((a)[0]), "r"((a)[1]), "r"((a)[2]), "r"((a)[3]), "r"(b0), "r"(b1))

// ---------------------------------------------------------------------------
// Prep: one warp per row. Computes rsqrt(sum sq) and max|x|, quantizes the
// row to int8 with q = round(x * 127 / max|x|) (rnorm cancels), and stores
// the combined dequant scale s = max|x| * rnorm / 127.
// Rows [0, NN*HWN): frame; rows [NN*HWN, NN*HWN+NN): audio.
// ---------------------------------------------------------------------------
__global__ void k_prep(const float* __restrict__ frame, const float* __restrict__ audio) {
    int gw = (blockIdx.x * blockDim.x + threadIdx.x) >> 5;
    int lane = threadIdx.x & 31;
    const float* src;
    int8_t* dst;
    float* sdst;
    if (gw < NN * HWN) {
        src = frame + (size_t)gw * CC;
        dst = g_qf + (size_t)gw * CC;
        sdst = g_sf + gw;
    } else {
        int r = gw - NN * HWN;
        if (r >= NN) return;
        src = audio + (size_t)r * CC;
        dst = g_qa + (size_t)r * CC;
        sdst = g_sa + r;
    }
    float4 v[4];
    float ss = 0.f, mx = 0.f;
#pragma unroll
    for (int p = 0; p < 4; p++) {
        v[p] = *(const float4*)(src + p * 128 + lane * 4);
        ss += v[p].x * v[p].x + v[p].y * v[p].y + v[p].z * v[p].z + v[p].w * v[p].w;
        mx = fmaxf(mx, fmaxf(fmaxf(fabsf(v[p].x), fabsf(v[p].y)),
                             fmaxf(fabsf(v[p].z), fabsf(v[p].w))));
    }
#pragma unroll
    for (int o = 16; o; o >>= 1) {
        ss += __shfl_xor_sync(0xffffffffu, ss, o);
        mx = fmaxf(mx, __shfl_xor_sync(0xffffffffu, mx, o));
    }
    float inv = 127.0f / mx;
#pragma unroll
    for (int p = 0; p < 4; p++) {
        int q0 = __float2int_rn(v[p].x * inv);
        int q1 = __float2int_rn(v[p].y * inv);
        int q2 = __float2int_rn(v[p].z * inv);
        int q3 = __float2int_rn(v[p].w * inv);
        uint32_t pk = (uint32_t)(q0 & 0xff) | ((uint32_t)(q1 & 0xff) << 8) |
                      ((uint32_t)(q2 & 0xff) << 16) | ((uint32_t)(q3 & 0xff) << 24);
        *(uint32_t*)(dst + p * 128 + lane * 4) = pk;
    }
    if (lane == 0) *sdst = mx * rsqrtf(ss) * (1.0f / 127.0f);
}

// ---------------------------------------------------------------------------
// Main: CTA (h, n) computes S[n, aud 0..255, hw half h] via int8 m16n8k32.
// Dequant (audio scale x frame scale, norms included) + sigmoid reductions
// fused in the epilogue.
// ---------------------------------------------------------------------------
__global__ void __launch_bounds__(256) k_mainTC() {
    extern __shared__ char sm[];
    uint32_t sb = smem_u32(sm);
    int tid = threadIdx.x;
    int lane = tid & 31;
    int w = tid >> 5;
    int gID = lane >> 2;
    int tig = lane & 3;
    int h = blockIdx.x;        // 0..1
    int n = blockIdx.y;        // 0..255

    const int8_t* fq = g_qf + ((size_t)n * HWN + h * HWH) * CC;
    int aud_off = (w >> 1) * 64;
    int hw_off  = (w & 1) * 56;

#define ISSUE(CH) do {                                                              \
    int _c = (CH);                                                                   \
    if (_c < 8) {                                                                    \
        int _st = _c % 3;                                                            \
        int _c0 = _c * 64;                                                           \
        uint32_t _a = sb + SM_A(_st);                                                \
        uint32_t _b = sb + SM_B(_st);                                                \
        _Pragma("unroll")                                                            \
        for (int j = 0; j < 4; j++) {                                                \
            int i = tid + j * 256;                                                   \
            int r = i >> 2, s = i & 3;                                               \
            CP_ASYNC16(_a + r * 80 + s * 16, g_qa + (size_t)r * CC + _c0 + s * 16);  \
        }                                                                            \
        _Pragma("unroll")                                                            \
        for (int j = 0; j < 2; j++) {                                                \
            int i = tid + j * 256;                                                   \
            if (i < 448) {                                                           \
                int r = i >> 2, s = i & 3;                                           \
                int rv = r < HWH ? r : HWH - 1;                                      \
                int sz = r < HWH ? 16 : 0;                                           \
                CP_ASYNC16Z(_b + r * 80 + s * 16,                                    \
                            fq + (size_t)rv * CC + _c0 + s * 16, sz);                \
            }                                                                        \
        }                                                                            \
    }                                                                                \
    CP_COMMIT();                                                                     \
} while (0)

    ISSUE(0); ISSUE(1); ISSUE(2);

    int acc[4][7][4];
#pragma unroll
    for (int mt = 0; mt < 4; mt++)
#pragma unroll
        for (int nt = 0; nt < 7; nt++)
#pragma unroll
            for (int e = 0; e < 4; e++) acc[mt][nt][e] = 0;

    for (int ch = 0; ch < 8; ch++) {
        int st = ch % 3;
        const char* Ab = sm + SM_A(st);
        const char* Bb = sm + SM_B(st);
        CP_WAIT2();
        __syncthreads();
#pragma unroll
        for (int ks = 0; ks < 2; ks++) {
            int kb = ks * 32 + tig * 4;
            uint32_t a[4][4];
#pragma unroll
            for (int mt = 0; mt < 4; mt++) {
                int r = aud_off + mt * 16 + gID;
                a[mt][0] = *(const uint32_t*)(Ab + r * 80 + kb);
                a[mt][1] = *(const uint32_t*)(Ab + (r + 8) * 80 + kb);
                a[mt][2] = *(const uint32_t*)(Ab + r * 80 + kb + 16);
                a[mt][3] = *(const uint32_t*)(Ab + (r + 8) * 80 + kb + 16);
            }
#pragma unroll
            for (int nt = 0; nt < 7; nt++) {
                int nr = hw_off + nt * 8 + gID;
                uint32_t b0 = *(const uint32_t*)(Bb + nr * 80 + kb);
                uint32_t b1 = *(const uint32_t*)(Bb + nr * 80 + kb + 16);
#pragma unroll
                for (int mt = 0; mt < 4; mt++) MMA_S8(acc[mt][nt], a[mt], b0, b1);
            }
        }
        __syncthreads();
        ISSUE(ch + 3);
    }

    // ---- scales + reduction buffers ----
    float* smA  = (float*)(sm + SM_SA);
    float* smF  = (float*)(sm + SM_SF);
    float* snum = (float*)(sm + SM_SNUM);
    float* sden = (float*)(sm + SM_SDEN);
    float* sneg = (float*)(sm + SM_SNEG);
    smA[tid] = g_sa[tid];
    if (tid < HWP) smF[tid] = (tid < HWH) ? g_sf[n * HWN + h * HWH + tid] : 0.f;
    snum[tid] = 0.f;
    sden[tid] = 0.f;
    if (tid == 0) { sneg[0] = 0.f; sneg[1] = 0.f; }
    __syncthreads();

    // ---- fused dequant + sigmoid epilogue ----
#pragma unroll
    for (int mt = 0; mt < 4; mt++) {
        int r0 = aud_off + mt * 16 + gID;
#pragma unroll
        for (int half = 0; half < 2; half++) {
            int r = r0 + half * 8;           // audio index
            bool isd = (r == n);
            float sa = smA[r];
            float pn = 0.f, pd = 0.f, qn = 0.f, qd = 0.f;
#pragma unroll
            for (int nt = 0; nt < 7; nt++) {
#pragma unroll
                for (int e = 0; e < 2; e++) {
                    int c = hw_off + nt * 8 + tig * 2 + e;
                    if (c < HWH) {
                        float S = (float)acc[mt][nt][half * 2 + e] * sa * smF[c];
                        float wg = __fdividef(1.f, 1.f + __expf((EPS_POS_F - S) * INV_TAU));
                        pn += wg * S;
                        pd += wg;
                        if (isd) {
                            float sp = __fdividef(1.f, 1.f + __expf((EPS_NEG_F - S) * INV_TAU));
                            float ng = 1.f - sp;
                            qn += ng * S;
                            qd += ng;
                        }
                    }
                }
            }
#pragma unroll
            for (int o = 1; o < 4; o <<= 1) {
                pn += __shfl_xor_sync(0xffffffffu, pn, o, 4);
                pd += __shfl_xor_sync(0xffffffffu, pd, o, 4);
                qn += __shfl_xor_sync(0xffffffffu, qn, o, 4);
                qd += __shfl_xor_sync(0xffffffffu, qd, o, 4);
            }
            if (tig == 0) {
                atomicAdd(&snum[r], pn);
                atomicAdd(&sden[r], pd);
                if (isd) { atomicAdd(&sneg[0], qn); atomicAdd(&sneg[1], qd); }
            }
        }
    }
    __syncthreads();
    g_pn[(size_t)h * NN * NN + (size_t)n * NN + tid] = snum[tid];
    g_pd[(size_t)h * NN * NN + (size_t)n * NN + tid] = sden[tid];
    if (tid == 0) {
        g_qn[h * NN + n] = sneg[0];
        g_qd[h * NN + n] = sneg[1];
    }
}

// ---------------------------------------------------------------------------
// Kernel D: per-n logits Pi_d, Ni_d (sum the two hw-half partials)
// ---------------------------------------------------------------------------
__global__ void k_rowreduce() {
    int n = blockIdx.x;
    int tid = threadIdx.x;   // 256
    float num = g_pn[(size_t)n * NN + tid] + g_pn[NN * NN + (size_t)n * NN + tid];
    float den = g_pd[(size_t)n * NN + tid] + g_pd[NN * NN + (size_t)n * NN + tid];
    float ratio = num / den;
    __shared__ float sPi[2];
    if (tid == n) { sPi[0] = num; sPi[1] = den; }
    float contrib = (tid == n) ? ratio * (-99.f) : ratio;
#pragma unroll
    for (int o = 16; o; o >>= 1) contrib += __shfl_xor_sync(0xffffffffu, contrib, o);
    __shared__ float sred[8];
    if ((tid & 31) == 0) sred[tid >> 5] = contrib;
    __syncthreads();
    if (tid == 0) {
        float r = 0.f;
#pragma unroll
        for (int i = 0; i < 8; i++) r += sred[i];
        float Pi = sPi[0] / sPi[1];
        float Nh = (g_qn[n] + g_qn[NN + n]) / (g_qd[n] + g_qd[NN + n]);
        g_Pid[n] = TEMP_F * Pi;
        g_Nid[n] = TEMP_F * (Nh + r);
    }
}

// ---------------------------------------------------------------------------
// Kernel E: (N,1)+(N,) broadcast -> sum softplus over all (n,k) pairs.
// 1024 threads: thread = (n, quarter of k range).
// ---------------------------------------------------------------------------
__global__ void k_loss(float* __restrict__ out) {
    int tid = threadIdx.x;   // 1024
    __shared__ float sN[256], sP[256];
    if (tid < 256) { sN[tid] = g_Nid[tid]; sP[tid] = g_Pid[tid]; }
    __syncthreads();
    int nrow = tid >> 2, q = tid & 3;
    float pid = sP[nrow];
    float acc = 0.f;
#pragma unroll 8
    for (int k = q * 64; k < q * 64 + 64; k++) {
        float x = sN[k] - pid;
        float m = fmaxf(x, 0.f);
        acc += m + __logf(__expf(x - m) + __expf(-m));
    }
#pragma unroll
    for (int o = 16; o; o >>= 1) acc += __shfl_xor_sync(0xffffffffu, acc, o);
    __shared__ float sred[32];
    if ((tid & 31) == 0) sred[tid >> 5] = acc;
    __syncthreads();
    if (tid == 0) {
        float s = 0.f;
#pragma unroll
        for (int i = 0; i < 32; i++) s += sred[i];
        out[0] = s * (1.0f / NN);
    }
}

extern "C" void kernel_launch(void* const* d_in, const int* in_sizes, int n_in,
                              void* d_out, int out_size) {
    const float* frame = (const float*)d_in[0];
    const float* audio = (const float*)d_in[1];
    if (n_in >= 2 && in_sizes[0] < in_sizes[1]) {
        frame = (const float*)d_in[1];
        audio = (const float*)d_in[0];
    }
    float* out = (float*)d_out;

    cudaFuncSetAttribute(k_mainTC, cudaFuncAttributeMaxDynamicSharedMemorySize, SMEM_TOTAL);

    int total_rows = NN * HWN + NN;             // frame + audio rows
    int blocks = (total_rows + 7) / 8;          // 8 warps per block
    k_prep<<<blocks, 256>>>(frame, audio);
    dim3 g(2, NN);
    k_mainTC<<<g, 256, SMEM_TOTAL>>>();
    k_rowreduce<<<NN, 256>>>();
    k_loss<<<1, 1024>>>(out);
}

// round 7
// speedup vs baseline: 1.5082x; 1.5082x over previous
#include <cuda_runtime.h>
#include <cuda_fp16.h>
#include <cstdint>
#include <math.h>

#define NN   256
#define HWN  196
#define CC   512
#define HWH  98            // real hw rows per half
#define HWP  112           // padded hw rows per half (14 x n8)
#define EPS_POS_F 0.65f
#define EPS_NEG_F 0.40f
#define INV_TAU   (1.0f/0.03f)
#define TEMP_F    0.07f

// ---- smem layout (bytes) ----
#define A_STAGE   20480        // 256 rows x 80 B (40 fp16, stride-padded)
#define BST_STAGE 16128        // 112 rows x 144 B (36 fp32)
#define SM_A(st)   ((st)*A_STAGE)
#define SM_BST(st) (61440 + (st)*BST_STAGE)
#define SM_BF16    109824      // 112 rows x 80 B fp16
#define SM_SNORM   118784      // float[112]
#define SM_RNS     119232      // float[112]
#define SM_SNUM    119680      // float[256]
#define SM_SDEN    120704      // float[256]
#define SM_SNEG    121728      // float[2]
#define SMEM_TOTAL 121760

// ---- scratch globals ----
__device__ __half g_aH[NN * CC];          // normalized audio fp16
__device__ float g_pn[2 * NN * NN];       // per-half partial num
__device__ float g_pd[2 * NN * NN];       // per-half partial den
__device__ float g_qn[2 * NN];            // per-half partial negnum
__device__ float g_qd[2 * NN];
__device__ float g_Pid[NN];
__device__ float g_Nid[NN];

__device__ __forceinline__ uint32_t smem_u32(const void* p) {
    uint32_t a;
    asm("{ .reg .u64 t; cvta.to.shared.u64 t, %1; cvt.u32.u64 %0, t; }" : "=r"(a) : "l"(p));
    return a;
}

#define CP_ASYNC16(dst, src) \
    asm volatile("cp.async.cg.shared.global [%0], [%1], 16;" :: "r"(dst), "l"(src) : "memory")
#define CP_ASYNC16Z(dst, src, sz) \
    asm volatile("cp.async.cg.shared.global [%0], [%1], 16, %2;" :: "r"(dst), "l"(src), "r"(sz) : "memory")
#define CP_COMMIT() asm volatile("cp.async.commit_group;" ::: "memory")
#define CP_WAIT2()  asm volatile("cp.async.wait_group 2;" ::: "memory")

// fp16 MMA with fp16 accumulators (2 output regs = 2x half2)
#define MMA_FP16ACC(d, a, b0, b1)                                               \
    asm volatile("mma.sync.aligned.m16n8k16.row.col.f16.f16.f16.f16 "           \
        "{%0,%1}, {%2,%3,%4,%5}, {%6,%7}, {%0,%1};"                             \
        : "+r"((d)[0]), "+r"((d)[1])                                            \
        : "r"((a)[0]), "r"((a)[1]), "r"((a)[2]), "r"((a)[3]), "r"(b0), "r"(b1))

// ---------------------------------------------------------------------------
// Kernel A: normalize audio -> fp16 row-major [k][c]
// ---------------------------------------------------------------------------
__global__ void k_audio(const float* __restrict__ audio) {
    int k = blockIdx.x;
    int tid = threadIdx.x;  // 128
    float4 v = *(const float4*)(audio + (size_t)k * CC + tid * 4);
    float ss = v.x * v.x + v.y * v.y + v.z * v.z + v.w * v.w;
#pragma unroll
    for (int o = 16; o; o >>= 1) ss += __shfl_xor_sync(0xffffffffu, ss, o);
    __shared__ float sred[4];
    if ((tid & 31) == 0) sred[tid >> 5] = ss;
    __syncthreads();
    float rn = rsqrtf(sred[0] + sred[1] + sred[2] + sred[3]);
    __half2 p0 = __float22half2_rn(make_float2(v.x * rn, v.y * rn));
    __half2 p1 = __float22half2_rn(make_float2(v.z * rn, v.w * rn));
    uint2 u;
    u.x = *reinterpret_cast<uint32_t*>(&p0);
    u.y = *reinterpret_cast<uint32_t*>(&p1);
    *(uint2*)(g_aH + (size_t)k * CC + tid * 4) = u;
}

// ---------------------------------------------------------------------------
// Main kernel: CTA (h, n) computes S[n, aud 0..255, hw half h] via fp16
// m16n8k16 mma.sync with FP16 accumulators. Frame converted fp32->fp16
// in-loop; row norms from raw fp32; sigmoid reductions fused.
// ---------------------------------------------------------------------------
__global__ void __launch_bounds__(256) k_mainTC(const float* __restrict__ frame) {
    extern __shared__ char sm[];
    uint32_t sb = smem_u32(sm);
    int tid = threadIdx.x;
    int lane = tid & 31;
    int w = tid >> 5;
    int gID = lane >> 2;
    int tig = lane & 3;
    int h = blockIdx.x;        // 0..1 hw half
    int n = blockIdx.y;        // 0..255

    const float* fbase = frame + ((size_t)n * HWN + h * HWH) * CC;
    int aud_off = (w >> 1) * 64;   // 4 aud groups of 64 rows
    int hw_off  = (w & 1) * 56;    // 2 hw groups of 56 cols

#define ISSUE(CH) do {                                                              \
    int _c = (CH);                                                                   \
    if (_c < 16) {                                                                   \
        int _st = _c % 3;                                                            \
        int _c0 = _c * 32;                                                           \
        uint32_t _a = sb + SM_A(_st);                                                \
        uint32_t _b = sb + SM_BST(_st);                                              \
        _Pragma("unroll")                                                            \
        for (int j = 0; j < 4; j++) {                                                \
            int i = tid + j * 256;                                                   \
            int r = i >> 2, s = i & 3;                                               \
            CP_ASYNC16(_a + r * 80 + s * 16, g_aH + (size_t)r * CC + _c0 + s * 8);   \
        }                                                                            \
        _Pragma("unroll")                                                            \
        for (int j = 0; j < 4; j++) {                                                \
            int i = tid + j * 256;                                                   \
            if (i < 896) {                                                           \
                int r = i >> 3, s = i & 7;                                           \
                int rv = r < HWH ? r : HWH - 1;                                      \
                int sz = r < HWH ? 16 : 0;                                           \
                CP_ASYNC16Z(_b + r * 144 + s * 16,                                   \
                            fbase + (size_t)rv * CC + _c0 + s * 4, sz);              \
            }                                                                        \
        }                                                                            \
    }                                                                                \
    CP_COMMIT();                                                                     \
} while (0)

    ISSUE(0); ISSUE(1); ISSUE(2);

    uint32_t acc[4][7][2];     // f16x2 accumulators
#pragma unroll
    for (int mt = 0; mt < 4; mt++)
#pragma unroll
        for (int nt = 0; nt < 7; nt++) { acc[mt][nt][0] = 0u; acc[mt][nt][1] = 0u; }
    float nrm[4];
#pragma unroll
    for (int j = 0; j < 4; j++) nrm[j] = 0.f;

    for (int ch = 0; ch < 16; ch++) {
        int st = ch % 3;
        CP_WAIT2();
        __syncthreads();

        // ---- convert fp32 staging -> fp16 B + norm accumulation ----
#pragma unroll
        for (int j = 0; j < 4; j++) {
            int i = tid + j * 256;
            if (i < 896) {
                int r = i >> 3, s = i & 7;
                float4 v = *(const float4*)(sm + SM_BST(st) + r * 144 + s * 16);
                __half2 h01 = __float22half2_rn(make_float2(v.x, v.y));
                __half2 h23 = __float22half2_rn(make_float2(v.z, v.w));
                uint2 u;
                u.x = *reinterpret_cast<uint32_t*>(&h01);
                u.y = *reinterpret_cast<uint32_t*>(&h23);
                *(uint2*)(sm + SM_BF16 + r * 80 + s * 8) = u;
                nrm[j] += v.x * v.x + v.y * v.y + v.z * v.z + v.w * v.w;
            }
        }
        __syncthreads();

        // ---- MMA phase: 2 k16-steps ----
        const char* Ab = sm + SM_A(st);
        const char* Bb = sm + SM_BF16;
#pragma unroll
        for (int ks = 0; ks < 2; ks++) {
            int kb = (ks * 16 + 2 * tig) * 2;    // byte offset of k pair
            uint32_t a[4][4];
#pragma unroll
            for (int mt = 0; mt < 4; mt++) {
                int r = aud_off + mt * 16 + gID;
                a[mt][0] = *(const uint32_t*)(Ab + r * 80 + kb);
                a[mt][1] = *(const uint32_t*)(Ab + (r + 8) * 80 + kb);
                a[mt][2] = *(const uint32_t*)(Ab + r * 80 + kb + 16);
                a[mt][3] = *(const uint32_t*)(Ab + (r + 8) * 80 + kb + 16);
            }
#pragma unroll
            for (int nt = 0; nt < 7; nt++) {
                int nr = hw_off + nt * 8 + gID;
                uint32_t b0 = *(const uint32_t*)(Bb + nr * 80 + kb);
                uint32_t b1 = *(const uint32_t*)(Bb + nr * 80 + kb + 16);
#pragma unroll
                for (int mt = 0; mt < 4; mt++) MMA_FP16ACC(acc[mt][nt], a[mt], b0, b1);
            }
        }
        __syncthreads();
        ISSUE(ch + 3);
    }

    // ---- finalize frame norms ----
    float* snorm = (float*)(sm + SM_SNORM);
    float* rns   = (float*)(sm + SM_RNS);
    float* snum  = (float*)(sm + SM_SNUM);
    float* sden  = (float*)(sm + SM_SDEN);
    float* sneg  = (float*)(sm + SM_SNEG);
#pragma unroll
    for (int j = 0; j < 4; j++) {
        int i = tid + j * 256;
        if (i < 896) {
            float v = nrm[j];
            v += __shfl_xor_sync(0xffffffffu, v, 1, 8);
            v += __shfl_xor_sync(0xffffffffu, v, 2, 8);
            v += __shfl_xor_sync(0xffffffffu, v, 4, 8);
            if ((tid & 7) == 0) snorm[i >> 3] = v;
        }
    }
    __syncthreads();
    if (tid < HWP) rns[tid] = (tid < HWH) ? rsqrtf(snorm[tid]) : 0.f;
    snum[tid] = 0.f;
    sden[tid] = 0.f;
    if (tid == 0) { sneg[0] = 0.f; sneg[1] = 0.f; }
    __syncthreads();

    // ---- fused sigmoid epilogue ----
#pragma unroll
    for (int mt = 0; mt < 4; mt++) {
        int r0 = aud_off + mt * 16 + gID;
#pragma unroll
        for (int half = 0; half < 2; half++) {
            int r = r0 + half * 8;           // audio index k
            bool isd = (r == n);
            float pn = 0.f, pd = 0.f, qn = 0.f, qd = 0.f;
#pragma unroll
            for (int nt = 0; nt < 7; nt++) {
                uint32_t pk = acc[mt][nt][half];
                float2 fv = __half22float2(*reinterpret_cast<__half2*>(&pk));
#pragma unroll
                for (int e = 0; e < 2; e++) {
                    int c = hw_off + nt * 8 + tig * 2 + e;
                    if (c < HWH) {
                        float S = (e ? fv.y : fv.x) * rns[c];
                        float wg = __fdividef(1.f, 1.f + __expf((EPS_POS_F - S) * INV_TAU));
                        pn += wg * S;
                        pd += wg;
                        if (isd) {
                            float sp = __fdividef(1.f, 1.f + __expf((EPS_NEG_F - S) * INV_TAU));
                            float ng = 1.f - sp;
                            qn += ng * S;
                            qd += ng;
                        }
                    }
                }
            }
#pragma unroll
            for (int o = 1; o < 4; o <<= 1) {
                pn += __shfl_xor_sync(0xffffffffu, pn, o, 4);
                pd += __shfl_xor_sync(0xffffffffu, pd, o, 4);
                qn += __shfl_xor_sync(0xffffffffu, qn, o, 4);
                qd += __shfl_xor_sync(0xffffffffu, qd, o, 4);
            }
            if (tig == 0) {
                atomicAdd(&snum[r], pn);
                atomicAdd(&sden[r], pd);
                if (isd) { atomicAdd(&sneg[0], qn); atomicAdd(&sneg[1], qd); }
            }
        }
    }
    __syncthreads();
    g_pn[(size_t)h * NN * NN + (size_t)n * NN + tid] = snum[tid];
    g_pd[(size_t)h * NN * NN + (size_t)n * NN + tid] = sden[tid];
    if (tid == 0) {
        g_qn[h * NN + n] = sneg[0];
        g_qd[h * NN + n] = sneg[1];
    }
}

// ---------------------------------------------------------------------------
// Kernel D: per-n logits Pi_d, Ni_d (sum the two hw-half partials)
// ---------------------------------------------------------------------------
__global__ void k_rowreduce() {
    int n = blockIdx.x;
    int tid = threadIdx.x;   // 256
    float num = g_pn[(size_t)n * NN + tid] + g_pn[NN * NN + (size_t)n * NN + tid];
    float den = g_pd[(size_t)n * NN + tid] + g_pd[NN * NN + (size_t)n * NN + tid];
    float ratio = num / den;
    __shared__ float sPi[2];
    if (tid == n) { sPi[0] = num; sPi[1] = den; }
    float contrib = (tid == n) ? ratio * (-99.f) : ratio;
#pragma unroll
    for (int o = 16; o; o >>= 1) contrib += __shfl_xor_sync(0xffffffffu, contrib, o);
    __shared__ float sred[8];
    if ((tid & 31) == 0) sred[tid >> 5] = contrib;
    __syncthreads();
    if (tid == 0) {
        float r = 0.f;
#pragma unroll
        for (int i = 0; i < 8; i++) r += sred[i];
        float Pi = sPi[0] / sPi[1];
        float Nh = (g_qn[n] + g_qn[NN + n]) / (g_qd[n] + g_qd[NN + n]);
        g_Pid[n] = TEMP_F * Pi;
        g_Nid[n] = TEMP_F * (Nh + r);
    }
}

// ---------------------------------------------------------------------------
// Kernel E: (N,1)+(N,) broadcast -> sum softplus over all (n,k) pairs.
// 1024 threads: thread = (n, quarter of k range).
// ---------------------------------------------------------------------------
__global__ void k_loss(float* __restrict__ out) {
    int tid = threadIdx.x;   // 1024
    __shared__ float sN[256], sP[256];
    if (tid < 256) { sN[tid] = g_Nid[tid]; sP[tid] = g_Pid[tid]; }
    __syncthreads();
    int nrow = tid >> 2, q = tid & 3;
    float pid = sP[nrow];
    float acc = 0.f;
#pragma unroll 8
    for (int k = q * 64; k < q * 64 + 64; k++) {
        float x = sN[k] - pid;
        float m = fmaxf(x, 0.f);
        acc += m + __logf(__expf(x - m) + __expf(-m));
    }
#pragma unroll
    for (int o = 16; o; o >>= 1) acc += __shfl_xor_sync(0xffffffffu, acc, o);
    __shared__ float sred[32];
    if ((tid & 31) == 0) sred[tid >> 5] = acc;
    __syncthreads();
    if (tid == 0) {
        float s = 0.f;
#pragma unroll
        for (int i = 0; i < 32; i++) s += sred[i];
        out[0] = s * (1.0f / NN);
    }
}

extern "C" void kernel_launch(void* const* d_in, const int* in_sizes, int n_in,
                              void* d_out, int out_size) {
    const float* frame = (const float*)d_in[0];
    const float* audio = (const float*)d_in[1];
    if (n_in >= 2 && in_sizes[0] < in_sizes[1]) {
        frame = (const float*)d_in[1];
        audio = (const float*)d_in[0];
    }
    float* out = (float*)d_out;

    cudaFuncSetAttribute(k_mainTC, cudaFuncAttributeMaxDynamicSharedMemorySize, SMEM_TOTAL);

    k_audio<<<NN, 128>>>(audio);
    dim3 g(2, NN);
    k_mainTC<<<g, 256, SMEM_TOTAL>>>(frame);
    k_rowreduce<<<NN, 256>>>();
    k_loss<<<1, 1024>>>(out);
}

// round 8
// speedup vs baseline: 1.9576x; 1.2980x over previous
#include <cuda_runtime.h>
#include <cuda_fp16.h>
#include <cstdint>
#include <math.h>

#define NN   256
#define HWN  196
#define CC   512
#define NROWS (NN * HWN)       // 50176 = 392 * 128
#define NBLK  392
#define MROWS 128
#define EPS_POS_F 0.65f
#define EPS_NEG_F 0.40f
#define INV_TAU   (1.0f/0.03f)
#define TEMP_F    0.07f

// ---- smem layout (bytes): 2-stage, all double-buffered ----
#define SM_A(st)    ((st) * 20480)             // audio fp16: 256 x 80B
#define SM_BST(st)  (40960 + (st) * 18432)     // frame fp32 staging: 128 x 144B
#define SM_BF16(st) (77824 + (st) * 10240)     // frame fp16: 128 x 80B
#define SM_RNS      98304                      // float[128]
#define SM_SNUM     98816                      // float[2][256]
#define SM_SDEN     100864                     // float[2][256]
#define SM_SNEG     102912                     // float[4]
#define SMEM_TOTAL  102928

// ---- scratch globals ----
__device__ __half g_aH[NN * CC];          // normalized audio fp16
__device__ float g_pn2[NBLK * 2 * NN];    // per-block, per-segment partial num
__device__ float g_pd2[NBLK * 2 * NN];
__device__ float g_qn2[NBLK * 2];
__device__ float g_qd2[NBLK * 2];
__device__ float g_Pid[NN];
__device__ float g_Nid[NN];
__device__ float g_lpart[32];

__device__ __forceinline__ uint32_t smem_u32(const void* p) {
    uint32_t a;
    asm("{ .reg .u64 t; cvta.to.shared.u64 t, %1; cvt.u32.u64 %0, t; }" : "=r"(a) : "l"(p));
    return a;
}

#define CP_ASYNC16(dst, src) \
    asm volatile("cp.async.cg.shared.global [%0], [%1], 16;" :: "r"(dst), "l"(src) : "memory")
#define CP_COMMIT() asm volatile("cp.async.commit_group;" ::: "memory")
#define CP_WAIT1()  asm volatile("cp.async.wait_group 1;" ::: "memory")

// fp16 MMA with fp16 accumulators
#define MMA_FP16ACC(d, a, b0, b1)                                               \
    asm volatile("mma.sync.aligned.m16n8k16.row.col.f16.f16.f16.f16 "           \
        "{%0,%1}, {%2,%3,%4,%5}, {%6,%7}, {%0,%1};"                             \
        : "+r"((d)[0]), "+r"((d)[1])                                            \
        : "r"((a)[0]), "r"((a)[1]), "r"((a)[2]), "r"((a)[3]), "r"(b0), "r"(b1))

// ---------------------------------------------------------------------------
// Kernel A: normalize audio -> fp16 row-major [k][c]
// ---------------------------------------------------------------------------
__global__ void k_audio(const float* __restrict__ audio) {
    int k = blockIdx.x;
    int tid = threadIdx.x;  // 128
    float4 v = *(const float4*)(audio + (size_t)k * CC + tid * 4);
    float ss = v.x * v.x + v.y * v.y + v.z * v.z + v.w * v.w;
#pragma unroll
    for (int o = 16; o; o >>= 1) ss += __shfl_xor_sync(0xffffffffu, ss, o);
    __shared__ float sred[4];
    if ((tid & 31) == 0) sred[tid >> 5] = ss;
    __syncthreads();
    float rn = rsqrtf(sred[0] + sred[1] + sred[2] + sred[3]);
    __half2 p0 = __float22half2_rn(make_float2(v.x * rn, v.y * rn));
    __half2 p1 = __float22half2_rn(make_float2(v.z * rn, v.w * rn));
    uint2 u;
    u.x = *reinterpret_cast<uint32_t*>(&p0);
    u.y = *reinterpret_cast<uint32_t*>(&p1);
    *(uint2*)(g_aH + (size_t)k * CC + tid * 4) = u;
}

// ---------------------------------------------------------------------------
// Main: CTA b computes S[flat rows b*128..+128, audio 0..255].
// M = frame rows (A operand), N = audio (B operand), K = 512 in 16 chunks.
// Rows span <=2 n-values -> two segment accumulator sets.
// ---------------------------------------------------------------------------
__global__ void __launch_bounds__(256) k_mainTC(const float* __restrict__ frame) {
    extern __shared__ char sm[];
    uint32_t sb = smem_u32(sm);
    int tid = threadIdx.x;
    int lane = tid & 31;
    int w = tid >> 5;
    int gID = lane >> 2;
    int tig = lane & 3;
    int blk = blockIdx.x;          // 0..391

    const float* fbase = frame + (size_t)blk * MROWS * CC;
    int m_off = (w >> 2) * 64;     // 2 m-groups of 64 rows
    int n_off = (w & 3) * 64;      // 4 n-groups of 64 audio cols

#define ISSUE(CH) do {                                                              \
    int _c = (CH);                                                                   \
    if (_c < 16) {                                                                   \
        int _st = _c & 1;                                                            \
        int _c0 = _c * 32;                                                           \
        uint32_t _a = sb + SM_A(_st);                                                \
        uint32_t _b = sb + SM_BST(_st);                                              \
        _Pragma("unroll")                                                            \
        for (int j = 0; j < 4; j++) {                                                \
            int i = tid + j * 256;                                                   \
            int r = i >> 2, s = i & 3;                                               \
            CP_ASYNC16(_a + r * 80 + s * 16, g_aH + (size_t)r * CC + _c0 + s * 8);   \
        }                                                                            \
        _Pragma("unroll")                                                            \
        for (int j = 0; j < 4; j++) {                                                \
            int i = tid + j * 256;                                                   \
            int r = i >> 3, s = i & 7;                                               \
            CP_ASYNC16(_b + r * 144 + s * 16, fbase + (size_t)r * CC + _c0 + s * 4); \
        }                                                                            \
    }                                                                                \
    CP_COMMIT();                                                                     \
} while (0)

    ISSUE(0); ISSUE(1);

    uint32_t acc[4][8][2];     // [mt][nt][half] f16x2
#pragma unroll
    for (int mt = 0; mt < 4; mt++)
#pragma unroll
        for (int nt = 0; nt < 8; nt++) { acc[mt][nt][0] = 0u; acc[mt][nt][1] = 0u; }
    float nrm[4];
#pragma unroll
    for (int j = 0; j < 4; j++) nrm[j] = 0.f;

    for (int ch = 0; ch < 16; ch++) {
        int st = ch & 1;
        CP_WAIT1();
        __syncthreads();

        // ---- convert fp32 staging -> fp16 + row-norm partials ----
#pragma unroll
        for (int j = 0; j < 4; j++) {
            int i = tid + j * 256;
            int r = i >> 3, s = i & 7;
            float4 v = *(const float4*)(sm + SM_BST(st) + r * 144 + s * 16);
            __half2 h01 = __float22half2_rn(make_float2(v.x, v.y));
            __half2 h23 = __float22half2_rn(make_float2(v.z, v.w));
            uint2 u;
            u.x = *reinterpret_cast<uint32_t*>(&h01);
            u.y = *reinterpret_cast<uint32_t*>(&h23);
            *(uint2*)(sm + SM_BF16(st) + r * 80 + s * 8) = u;
            nrm[j] += v.x * v.x + v.y * v.y + v.z * v.z + v.w * v.w;
        }
        __syncthreads();

        // ---- MMA: 2 k16-steps, A=frame(BF16), B=audio(A-tile) ----
        const char* Ab = sm + SM_BF16(st);
        const char* Bb = sm + SM_A(st);
#pragma unroll
        for (int ks = 0; ks < 2; ks++) {
            int kb = (ks * 16 + 2 * tig) * 2;
            uint32_t a[4][4];
#pragma unroll
            for (int mt = 0; mt < 4; mt++) {
                int r = m_off + mt * 16 + gID;
                a[mt][0] = *(const uint32_t*)(Ab + r * 80 + kb);
                a[mt][1] = *(const uint32_t*)(Ab + (r + 8) * 80 + kb);
                a[mt][2] = *(const uint32_t*)(Ab + r * 80 + kb + 16);
                a[mt][3] = *(const uint32_t*)(Ab + (r + 8) * 80 + kb + 16);
            }
#pragma unroll
            for (int nt = 0; nt < 8; nt++) {
                int nr = n_off + nt * 8 + gID;
                uint32_t b0 = *(const uint32_t*)(Bb + nr * 80 + kb);
                uint32_t b1 = *(const uint32_t*)(Bb + nr * 80 + kb + 16);
#pragma unroll
                for (int mt = 0; mt < 4; mt++) MMA_FP16ACC(acc[mt][nt], a[mt], b0, b1);
            }
        }
        __syncthreads();
        ISSUE(ch + 2);
    }

    // ---- finalize frame row norms (row = tid>>3 + j*32, unique writer) ----
    float* rns  = (float*)(sm + SM_RNS);
    float* snum = (float*)(sm + SM_SNUM);
    float* sden = (float*)(sm + SM_SDEN);
    float* sneg = (float*)(sm + SM_SNEG);
#pragma unroll
    for (int j = 0; j < 4; j++) {
        float v = nrm[j];
        v += __shfl_xor_sync(0xffffffffu, v, 1, 8);
        v += __shfl_xor_sync(0xffffffffu, v, 2, 8);
        v += __shfl_xor_sync(0xffffffffu, v, 4, 8);
        if ((tid & 7) == 0) rns[(tid >> 3) + j * 32] = rsqrtf(v);
    }
    snum[tid] = 0.f; snum[256 + tid] = 0.f;
    sden[tid] = 0.f; sden[256 + tid] = 0.f;
    if (tid < 4) sneg[tid] = 0.f;
    __syncthreads();

    // ---- fused sigmoid epilogue with 2-segment split ----
    int n_first = (blk * MROWS) / HWN;
    int nsplit  = (n_first + 1) * HWN - blk * MROWS;   // local row where n increments
    float qn0 = 0.f, qd0 = 0.f, qn1 = 0.f, qd1 = 0.f;

#pragma unroll
    for (int nt = 0; nt < 8; nt++) {
        float p[2][2] = {{0.f, 0.f}, {0.f, 0.f}};   // [e][seg]
        float d[2][2] = {{0.f, 0.f}, {0.f, 0.f}};
        int kbase = n_off + nt * 8 + tig * 2;
#pragma unroll
        for (int mt = 0; mt < 4; mt++) {
#pragma unroll
            for (int half = 0; half < 2; half++) {
                int row = m_off + mt * 16 + gID + half * 8;
                uint32_t pk = acc[mt][nt][half];
                float2 fv = __half22float2(*reinterpret_cast<__half2*>(&pk));
                float rn = rns[row];
                int seg = (row >= nsplit) ? 1 : 0;
                int nrow = n_first + seg;
#pragma unroll
                for (int e = 0; e < 2; e++) {
                    float S = (e ? fv.y : fv.x) * rn;
                    float wg = __fdividef(1.f, 1.f + __expf((EPS_POS_F - S) * INV_TAU));
                    p[e][seg] += wg * S;
                    d[e][seg] += wg;
                    if (kbase + e == nrow) {
                        float sp = __fdividef(1.f, 1.f + __expf((EPS_NEG_F - S) * INV_TAU));
                        float ng = 1.f - sp;
                        if (seg) { qn1 += ng * S; qd1 += ng; }
                        else     { qn0 += ng * S; qd0 += ng; }
                    }
                }
            }
        }
#pragma unroll
        for (int e = 0; e < 2; e++) {
#pragma unroll
            for (int o = 4; o < 32; o <<= 1) {
                p[e][0] += __shfl_xor_sync(0xffffffffu, p[e][0], o);
                d[e][0] += __shfl_xor_sync(0xffffffffu, d[e][0], o);
                p[e][1] += __shfl_xor_sync(0xffffffffu, p[e][1], o);
                d[e][1] += __shfl_xor_sync(0xffffffffu, d[e][1], o);
            }
            if (lane < 4) {
                int k = kbase + e;
                atomicAdd(&snum[k], p[e][0]);
                atomicAdd(&sden[k], d[e][0]);
                atomicAdd(&snum[256 + k], p[e][1]);
                atomicAdd(&sden[256 + k], d[e][1]);
            }
        }
    }
    // diag partials: reduce across warp, lane 0 adds
#pragma unroll
    for (int o = 1; o < 32; o <<= 1) {
        qn0 += __shfl_xor_sync(0xffffffffu, qn0, o);
        qd0 += __shfl_xor_sync(0xffffffffu, qd0, o);
        qn1 += __shfl_xor_sync(0xffffffffu, qn1, o);
        qd1 += __shfl_xor_sync(0xffffffffu, qd1, o);
    }
    if (lane == 0) {
        atomicAdd(&sneg[0], qn0); atomicAdd(&sneg[1], qd0);
        atomicAdd(&sneg[2], qn1); atomicAdd(&sneg[3], qd1);
    }
    __syncthreads();
    g_pn2[(size_t)blk * 512 + tid]       = snum[tid];
    g_pn2[(size_t)blk * 512 + 256 + tid] = snum[256 + tid];
    g_pd2[(size_t)blk * 512 + tid]       = sden[tid];
    g_pd2[(size_t)blk * 512 + 256 + tid] = sden[256 + tid];
    if (tid == 0) {
        g_qn2[blk * 2]     = sneg[0];
        g_qd2[blk * 2]     = sneg[1];
        g_qn2[blk * 2 + 1] = sneg[2];
        g_qd2[blk * 2 + 1] = sneg[3];
    }
}

// ---------------------------------------------------------------------------
// Kernel D: gather per-block partials -> per-n logits Pi_d, Ni_d
// ---------------------------------------------------------------------------
__global__ void k_rowreduce() {
    int n = blockIdx.x;
    int tid = threadIdx.x;   // 256 = k
    int r0 = n * HWN;
    int b0 = r0 >> 7;
    int b1 = (r0 + HWN - 1) >> 7;
    float num = 0.f, den = 0.f, qn = 0.f, qd = 0.f;
    for (int b = b0; b <= b1; b++) {
        int nf = (b << 7) / HWN;
        int seg = (n == nf) ? 0 : 1;
        num += g_pn2[(size_t)b * 512 + seg * 256 + tid];
        den += g_pd2[(size_t)b * 512 + seg * 256 + tid];
        qn  += g_qn2[b * 2 + seg];
        qd  += g_qd2[b * 2 + seg];
    }
    float ratio = num / den;
    __shared__ float sPi[2];
    if (tid == n) { sPi[0] = num; sPi[1] = den; }
    float contrib = (tid == n) ? ratio * (-99.f) : ratio;
#pragma unroll
    for (int o = 16; o; o >>= 1) contrib += __shfl_xor_sync(0xffffffffu, contrib, o);
    __shared__ float sred[8];
    if ((tid & 31) == 0) sred[tid >> 5] = contrib;
    __syncthreads();
    if (tid == 0) {
        float r = 0.f;
#pragma unroll
        for (int i = 0; i < 8; i++) r += sred[i];
        float Pi = sPi[0] / sPi[1];
        float Nh = qn / qd;
        g_Pid[n] = TEMP_F * Pi;
        g_Nid[n] = TEMP_F * (Nh + r);
    }
}

// ---------------------------------------------------------------------------
// Kernel E1: partial softplus sums. 32 blocks x 8 rows each.
// loss terms: softplus(Ni_d[k] - Pi_d[n]) over all pairs (n,k).
// ---------------------------------------------------------------------------
__global__ void k_loss_part() {
    int tid = threadIdx.x;   // 256 = 8 warps, warp w handles n = blk*8 + w
    int lane = tid & 31;
    int w = tid >> 5;
    __shared__ float sN[256];
    sN[tid] = g_Nid[tid];
    __syncthreads();
    int n = blockIdx.x * 8 + w;
    float pid = g_Pid[n];
    float acc = 0.f;
#pragma unroll
    for (int kk = 0; kk < 8; kk++) {
        float x = sN[lane + kk * 32] - pid;
        float m = fmaxf(x, 0.f);
        acc += m + __logf(__expf(x - m) + __expf(-m));
    }
#pragma unroll
    for (int o = 16; o; o >>= 1) acc += __shfl_xor_sync(0xffffffffu, acc, o);
    __shared__ float sred[8];
    if (lane == 0) sred[w] = acc;
    __syncthreads();
    if (tid == 0) {
        float s = 0.f;
#pragma unroll
        for (int i = 0; i < 8; i++) s += sred[i];
        g_lpart[blockIdx.x] = s;
    }
}

__global__ void k_loss_final(float* __restrict__ out) {
    int tid = threadIdx.x;   // 32
    float v = g_lpart[tid];
#pragma unroll
    for (int o = 16; o; o >>= 1) v += __shfl_xor_sync(0xffffffffu, v, o);
    if (tid == 0) out[0] = v * (1.0f / NN);
}

extern "C" void kernel_launch(void* const* d_in, const int* in_sizes, int n_in,
                              void* d_out, int out_size) {
    const float* frame = (const float*)d_in[0];
    const float* audio = (const float*)d_in[1];
    if (n_in >= 2 && in_sizes[0] < in_sizes[1]) {
        frame = (const float*)d_in[1];
        audio = (const float*)d_in[0];
    }
    float* out = (float*)d_out;

    cudaFuncSetAttribute(k_mainTC, cudaFuncAttributeMaxDynamicSharedMemorySize, SMEM_TOTAL);

    k_audio<<<NN, 128>>>(audio);
    k_mainTC<<<NBLK, 256, SMEM_TOTAL>>>(frame);
    k_rowreduce<<<NN, 256>>>();
    k_loss_part<<<32, 256>>>();
    k_loss_final<<<1, 32>>>(out);
}